// round 3
// baseline (speedup 1.0000x reference)
#include <cuda_runtime.h>

// Problem shape (fixed by the dataset)
#define BATCH 8
#define CH    256
#define HH    128
#define WW    128
#define HO    64
#define WO    64
#define NPLANES (BATCH * CH)
#define TILE_ROWS 4          // output rows per block
#define SROW 132             // padded smem row width (130 used)

// scratch for per-plane 1/(max|x|+1)
__device__ float g_inv_m[NPLANES];

__device__ __forceinline__ float f_lg2(float x) {
    float y; asm("lg2.approx.f32 %0, %1;" : "=f"(y) : "f"(x)); return y;
}
__device__ __forceinline__ float f_ex2(float x) {
    float y; asm("ex2.approx.f32 %0, %1;" : "=f"(y) : "f"(x)); return y;
}
__device__ __forceinline__ float f_rcp(float x) {
    float y; asm("rcp.approx.f32 %0, %1;" : "=f"(y) : "f"(x)); return y;
}

// Kernel 1: per-(b,c) plane max of |x|, store 1/(max+1).
__global__ __launch_bounds__(256) void plane_max_kernel(const float* __restrict__ bottom) {
    int plane = blockIdx.x;
    const float4* p = (const float4*)(bottom + (size_t)plane * (HH * WW));
    float mx = 0.f;
    #pragma unroll 4
    for (int i = threadIdx.x; i < HH * WW / 4; i += 256) {
        float4 v = p[i];
        mx = fmaxf(mx, fmaxf(fmaxf(fabsf(v.x), fabsf(v.y)),
                             fmaxf(fabsf(v.z), fabsf(v.w))));
    }
    #pragma unroll
    for (int o = 16; o; o >>= 1) mx = fmaxf(mx, __shfl_xor_sync(0xffffffffu, mx, o));
    __shared__ float sm[8];
    if ((threadIdx.x & 31) == 0) sm[threadIdx.x >> 5] = mx;
    __syncthreads();
    if (threadIdx.x < 8) {
        mx = sm[threadIdx.x];
        #pragma unroll
        for (int o = 4; o; o >>= 1) mx = fmaxf(mx, __shfl_xor_sync(0xffu, mx, o));
        if (threadIdx.x == 0) g_inv_m[plane] = 1.0f / (mx + 1.0f);
    }
}

// Kernel 2: fused exponent branch (depthwise 3x3 s2 p1 conv on bottom/m,
// PReLU, per-channel affine, clamp) + p-pooling (power-mean with the same
// window geometry). One block = 64x4 output pixels of one plane.
__global__ __launch_bounds__(256) void ppool_kernel(
    const float* __restrict__ bottom,
    const float* __restrict__ w1,
    const float* __restrict__ a1,
    const float* __restrict__ w2,
    const float* __restrict__ b2,
    float* __restrict__ out_res,
    float* __restrict__ out_p)
{
    __shared__ float sval[9][SROW];   // raw values (for conv)
    __shared__ float slog[9][SROW];   // log2(relu(v)) (for pooling); -inf at 0
    __shared__ float swt[9];          // conv weights pre-scaled by 1/m

    const int hg = blockIdx.x;        // 0..15  (row group: 4 output rows)
    const int c  = blockIdx.y;
    const int b  = blockIdx.z;
    const int plane = b * CH + c;
    const float* __restrict__ src = bottom + (size_t)plane * (HH * WW);

    const int tx = threadIdx.x;       // 0..63 -> wo
    const int ty = threadIdx.y;       // 0..3  -> ho within group
    const int t  = ty * WO + tx;

    const int base = hg * (2 * TILE_ROWS);   // first input row needed is base-1
    const float invm = g_inv_m[plane];
    if (t < 9) swt[t] = __ldg(&w1[c * 9 + t]) * invm;

    // Cooperative tile load: 9 input rows x 130 cols (zero padded).
    // Fully-covering strided loop — every one of the 9*130 tile elements is
    // written exactly once (no holes).
    for (int idx = t; idx < 9 * 130; idx += 256) {
        int r  = idx / 130;
        int cc = idx - r * 130;
        int ih = base - 1 + r;
        int iw = cc - 1;
        float v = 0.f;
        if ((unsigned)ih < (unsigned)HH && (unsigned)iw < (unsigned)WW)
            v = __ldg(&src[ih * WW + iw]);
        sval[r][cc] = v;
        slog[r][cc] = f_lg2(fmaxf(v, 0.f));   // lg2(0) = -inf -> ex2 -> 0
    }
    __syncthreads();

    const int r0 = 2 * ty;
    const int c0 = 2 * tx;

    // Depthwise conv (weights already scaled by 1/m)
    float conv = 0.f;
    #pragma unroll
    for (int ki = 0; ki < 3; ki++)
        #pragma unroll
        for (int kj = 0; kj < 3; kj++)
            conv = fmaf(swt[ki * 3 + kj], sval[r0 + ki][c0 + kj], conv);

    // PReLU + per-channel affine + clamp -> exponent p
    float a = __ldg(&a1[c]);
    float x = conv > 0.f ? conv : a * conv;
    float p = fmaf(x, __ldg(&w2[c]), __ldg(&b2[c]));
    p = fminf(fmaxf(p, 1.0f), 110.0f);   // MIN_P/MAX_P round to these in fp32

    // Power-mean over the 3x3 window: sum relu(x)^p via shared log2 table
    float sum = 0.f;
    #pragma unroll
    for (int ki = 0; ki < 3; ki++)
        #pragma unroll
        for (int kj = 0; kj < 3; kj++)
            sum += f_ex2(p * slog[r0 + ki][c0 + kj]);

    float mean = fmaf(sum, (1.0f / 9.0f), 1e-12f);
    float res  = f_ex2(f_lg2(mean) * f_rcp(p));

    const int ho = hg * TILE_ROWS + ty;
    const size_t o = ((size_t)plane * HO + ho) * WO + tx;
    out_res[o] = res;
    out_p[o]   = p;
}

extern "C" void kernel_launch(void* const* d_in, const int* in_sizes, int n_in,
                              void* d_out, int out_size) {
    const float* bottom = (const float*)d_in[0];
    const float* w1     = (const float*)d_in[1];
    const float* a1     = (const float*)d_in[2];
    const float* w2     = (const float*)d_in[3];
    const float* b2     = (const float*)d_in[4];
    float* out = (float*)d_out;
    const size_t N = (size_t)BATCH * CH * HO * WO;   // elements per output tensor

    plane_max_kernel<<<NPLANES, 256>>>(bottom);

    dim3 grid(HO / TILE_ROWS, CH, BATCH);
    dim3 blk(WO, TILE_ROWS);
    ppool_kernel<<<grid, blk>>>(bottom, w1, a1, w2, b2, out, out + N);

    (void)in_sizes; (void)n_in; (void)out_size;
}

// round 6
// speedup vs baseline: 1.1375x; 1.1375x over previous
#include <cuda_runtime.h>

// Problem shape (fixed by the dataset)
#define BATCH 8
#define CH    256
#define HH    128
#define WW    128
#define HO    64
#define WO    64
#define NPLANES (BATCH * CH)
#define TR    8               // output rows per block
#define TROWS (2 * TR + 1)    // input tile rows = 17

// scratch for per-plane 1/(max|x|+1)
__device__ float g_inv_m[NPLANES];

__device__ __forceinline__ float f_lg2(float x) {
    float y; asm("lg2.approx.f32 %0, %1;" : "=f"(y) : "f"(x)); return y;
}
__device__ __forceinline__ float f_ex2(float x) {
    float y; asm("ex2.approx.f32 %0, %1;" : "=f"(y) : "f"(x)); return y;
}
__device__ __forceinline__ float f_rcp(float x) {
    float y; asm("rcp.approx.f32 %0, %1;" : "=f"(y) : "f"(x)); return y;
}

// Kernel 1: per-(b,c) plane max of |x|, store 1/(max+1).
__global__ __launch_bounds__(512) void plane_max_kernel(const float* __restrict__ bottom) {
    int plane = blockIdx.x;
    const float4* p = (const float4*)(bottom + (size_t)plane * (HH * WW));
    float mx = 0.f;
    // 4096 float4 per plane / 512 threads = 8 per thread
    #pragma unroll 8
    for (int i = threadIdx.x; i < HH * WW / 4; i += 512) {
        float4 v = p[i];
        mx = fmaxf(mx, fmaxf(fmaxf(fabsf(v.x), fabsf(v.y)),
                             fmaxf(fabsf(v.z), fabsf(v.w))));
    }
    #pragma unroll
    for (int o = 16; o; o >>= 1) mx = fmaxf(mx, __shfl_xor_sync(0xffffffffu, mx, o));
    __shared__ float sm[16];
    if ((threadIdx.x & 31) == 0) sm[threadIdx.x >> 5] = mx;
    __syncthreads();
    if (threadIdx.x < 16) {
        mx = sm[threadIdx.x];
        #pragma unroll
        for (int o = 8; o; o >>= 1) mx = fmaxf(mx, __shfl_xor_sync(0xffffu, mx, o));
        if (threadIdx.x == 0) g_inv_m[plane] = 1.0f / (mx + 1.0f);
    }
}

// Kernel 2: fused exponent branch + p-pooling.
// Parity-split shared tiles holding {val, log2(relu(val))} pairs:
//   pe[r][k] = col 2k  (k=0..63), po[r][j] = col 2j-1 (j=0..64; j=0 = left pad)
// Window for output wo reads po[wo], pe[wo], po[wo+1] -> stride-1 LDS.64,
// conflict-free, one fetch serves both conv (.x) and pooling (.y).
__global__ __launch_bounds__(512) void ppool_kernel(
    const float* __restrict__ bottom,
    const float* __restrict__ w1,
    const float* __restrict__ a1,
    const float* __restrict__ w2,
    const float* __restrict__ b2,
    float* __restrict__ out_res,
    float* __restrict__ out_p)
{
    __shared__ float2 pe[TROWS][64];
    __shared__ float2 po[TROWS][65];
    __shared__ float  swt[9];          // conv weights pre-scaled by 1/m

    const int hg = blockIdx.x;        // 0..7  (row group: TR output rows)
    const int c  = blockIdx.y;
    const int b  = blockIdx.z;
    const int plane = b * CH + c;
    const float* __restrict__ src = bottom + (size_t)plane * (HH * WW);

    const int tx = threadIdx.x;       // 0..63 -> wo
    const int ty = threadIdx.y;       // 0..7  -> ho within group
    const int t  = ty * 64 + tx;      // 0..511

    const int base = hg * (2 * TR);   // first input row needed is base-1
    if (t < 9) swt[t] = __ldg(&w1[c * 9 + t]) * g_inv_m[plane];
    if (t < TROWS) {                  // left zero pad (col -1): val 0, log -inf
        po[t][0] = make_float2(0.f, __int_as_float(0xff800000));
    }

    // Cooperative vectorized tile load: TROWS rows x 64 float2 (cols 0..127).
    for (int idx = t; idx < TROWS * 64; idx += 512) {
        int r = idx >> 6;
        int k = idx & 63;
        int ih = base - 1 + r;
        float2 v = make_float2(0.f, 0.f);
        if ((unsigned)ih < (unsigned)HH)
            v = __ldg((const float2*)(src + ih * WW) + k);
        pe[r][k]     = make_float2(v.x, f_lg2(fmaxf(v.x, 0.f)));
        po[r][k + 1] = make_float2(v.y, f_lg2(fmaxf(v.y, 0.f)));
    }
    __syncthreads();

    const int r0 = 2 * ty;

    // Fetch the 9 window taps once each (LDS.64), then do conv + pooling.
    float2 w00, w01, w02, w10, w11, w12, w20, w21, w22;
    w00 = po[r0 + 0][tx]; w01 = pe[r0 + 0][tx]; w02 = po[r0 + 0][tx + 1];
    w10 = po[r0 + 1][tx]; w11 = pe[r0 + 1][tx]; w12 = po[r0 + 1][tx + 1];
    w20 = po[r0 + 2][tx]; w21 = pe[r0 + 2][tx]; w22 = po[r0 + 2][tx + 1];

    // Depthwise conv (weights already scaled by 1/m)
    float conv = swt[0] * w00.x;
    conv = fmaf(swt[1], w01.x, conv);
    conv = fmaf(swt[2], w02.x, conv);
    conv = fmaf(swt[3], w10.x, conv);
    conv = fmaf(swt[4], w11.x, conv);
    conv = fmaf(swt[5], w12.x, conv);
    conv = fmaf(swt[6], w20.x, conv);
    conv = fmaf(swt[7], w21.x, conv);
    conv = fmaf(swt[8], w22.x, conv);

    // PReLU + per-channel affine + clamp -> exponent p
    float a = __ldg(&a1[c]);
    float x = conv > 0.f ? conv : a * conv;
    float p = fmaf(x, __ldg(&w2[c]), __ldg(&b2[c]));
    p = fminf(fmaxf(p, 1.0f), 110.0f);   // MIN_P/MAX_P round to these in fp32

    // Power-mean over the 3x3 window: sum relu(x)^p = ex2(p * log2(relu(x)))
    float sum = f_ex2(p * w00.y);
    sum += f_ex2(p * w01.y);
    sum += f_ex2(p * w02.y);
    sum += f_ex2(p * w10.y);
    sum += f_ex2(p * w11.y);
    sum += f_ex2(p * w12.y);
    sum += f_ex2(p * w20.y);
    sum += f_ex2(p * w21.y);
    sum += f_ex2(p * w22.y);

    float mean = fmaf(sum, (1.0f / 9.0f), 1e-12f);
    float res  = f_ex2(f_lg2(mean) * f_rcp(p));

    const int ho = hg * TR + ty;
    const size_t o = ((size_t)plane * HO + ho) * WO + tx;
    out_res[o] = res;
    out_p[o]   = p;
}

extern "C" void kernel_launch(void* const* d_in, const int* in_sizes, int n_in,
                              void* d_out, int out_size) {
    const float* bottom = (const float*)d_in[0];
    const float* w1     = (const float*)d_in[1];
    const float* a1     = (const float*)d_in[2];
    const float* w2     = (const float*)d_in[3];
    const float* b2     = (const float*)d_in[4];
    float* out = (float*)d_out;
    const size_t N = (size_t)BATCH * CH * HO * WO;   // elements per output tensor

    plane_max_kernel<<<NPLANES, 512>>>(bottom);

    dim3 grid(HO / TR, CH, BATCH);
    dim3 blk(WO, TR);
    ppool_kernel<<<grid, blk>>>(bottom, w1, a1, w2, b2, out, out + N);

    (void)in_sizes; (void)n_in; (void)out_size;
}

// round 7
// speedup vs baseline: 1.6490x; 1.4497x over previous
#include <cuda_runtime.h>

// Problem shape (fixed by the dataset)
#define BATCH 8
#define CH    256
#define HH    128
#define WW    128
#define HO    64
#define WO    64
#define NPLANES 2048

// Dynamic smem layout (floats):
//   le[128][64]  : log2(relu(even cols)),  le[r][k] = col 2k
//   lo[128][65]  : log2(relu(odd cols)),   lo[r][j] = col 2j-1 (j=0 = left pad)
//   sc[48]       : [0..31] warp max partials, [32] invm, [33..41] w1 raw
#define LE_OFF 0
#define LO_OFF (128 * 64)
#define SC_OFF (LO_OFF + 128 * 65)
#define SMEM_FLOATS (SC_OFF + 48)
#define SMEM_BYTES  (SMEM_FLOATS * 4)

__device__ __forceinline__ float f_lg2(float x) {
    float y; asm("lg2.approx.f32 %0, %1;" : "=f"(y) : "f"(x)); return y;
}
__device__ __forceinline__ float f_ex2(float x) {
    float y; asm("ex2.approx.f32 %0, %1;" : "=f"(y) : "f"(x)); return y;
}
__device__ __forceinline__ float f_rcp(float x) {
    float y; asm("rcp.approx.f32 %0, %1;" : "=f"(y) : "f"(x)); return y;
}

// One block = one (b,c) plane. 1024 threads = (64, 16).
// Phase 1: stream plane once, build log table in smem + plane max.
// Phase 2: 4 outputs/thread; conv from L2-resident gmem, pooling from smem.
__global__ __launch_bounds__(1024, 2) void fused_ppool_kernel(
    const float* __restrict__ bottom,
    const float* __restrict__ w1,
    const float* __restrict__ a1,
    const float* __restrict__ w2,
    const float* __restrict__ b2,
    float* __restrict__ out_res,
    float* __restrict__ out_p)
{
    extern __shared__ float smem[];
    float* le = smem + LE_OFF;
    float* lo = smem + LO_OFF;
    float* sc = smem + SC_OFF;

    const int plane = blockIdx.x;
    const int c = plane & (CH - 1);
    const float* __restrict__ src = bottom + (size_t)plane * (HH * WW);

    const int tx = threadIdx.x;          // 0..63 -> wo
    const int ty = threadIdx.y;          // 0..15
    const int t  = ty * 64 + tx;         // 0..1023
    const int wid = t >> 5, lid = t & 31;

    if (t < 9)   sc[33 + t] = __ldg(&w1[c * 9 + t]);
    if (t < 128) lo[t * 65] = __int_as_float(0xff800000);  // col -1 pad: -inf

    // ---- Phase 1: plane streaming (8192 float2), log table + |x| max ----
    const float2* s2 = (const float2*)src;
    float mx = 0.f;
    #pragma unroll
    for (int i = 0; i < 8; i++) {
        int idx = t + i * 1024;          // float2 index: row = idx>>6, k = idx&63
        int r = idx >> 6, k = idx & 63;
        float2 v = __ldg(s2 + idx);
        le[r * 64 + k]     = f_lg2(fmaxf(v.x, 0.f));   // lg2(0) = -inf
        lo[r * 65 + k + 1] = f_lg2(fmaxf(v.y, 0.f));
        mx = fmaxf(mx, fmaxf(fabsf(v.x), fabsf(v.y)));
    }
    #pragma unroll
    for (int o = 16; o; o >>= 1) mx = fmaxf(mx, __shfl_xor_sync(0xffffffffu, mx, o));
    if (lid == 0) sc[wid] = mx;
    __syncthreads();
    if (t < 32) {
        float m = sc[t];
        #pragma unroll
        for (int o = 16; o; o >>= 1) m = fmaxf(m, __shfl_xor_sync(0xffffffffu, m, o));
        if (t == 0) sc[32] = 1.0f / (m + 1.0f);
    }
    __syncthreads();

    const float invm = sc[32];
    float w[9];
    #pragma unroll
    for (int i = 0; i < 9; i++) w[i] = sc[33 + i];
    const float av = __ldg(&a1[c]);
    const float wv = __ldg(&w2[c]);
    const float bv = __ldg(&b2[c]);

    // ---- Phase 2: 4 vertically-adjacent outputs per thread ----
    #pragma unroll
    for (int g = 0; g < 4; g++) {
        const int ho = (ty << 2) + g;
        const int rbase = 2 * ho - 1;

        // conv taps from gmem (L2-hot: this plane was just streamed)
        float conv = 0.f;
        #pragma unroll
        for (int ki = 0; ki < 3; ki++) {
            int r = rbase + ki;
            bool rv = (unsigned)r < (unsigned)HH;
            const float* rp = src + (rv ? r : 0) * WW + 2 * tx;
            float v0 = (rv && tx > 0) ? __ldg(rp - 1) : 0.f;
            float v1 = rv ? __ldg(rp)     : 0.f;
            float v2 = rv ? __ldg(rp + 1) : 0.f;
            conv = fmaf(w[ki * 3 + 0], v0, conv);
            conv = fmaf(w[ki * 3 + 1], v1, conv);
            conv = fmaf(w[ki * 3 + 2], v2, conv);
        }
        conv *= invm;                    // conv(x/m) = invm * conv_raw(x)

        // PReLU + per-channel affine + clamp -> exponent p
        float x = conv > 0.f ? conv : av * conv;
        float p = fmaf(x, wv, bv);
        p = fminf(fmaxf(p, 1.0f), 110.0f);

        // Power-mean over the 3x3 window from the smem log tables
        float sum = 0.f;
        #pragma unroll
        for (int ki = 0; ki < 3; ki++) {
            int r = rbase + ki;
            bool rv = (unsigned)r < (unsigned)HH;
            int ro = rv ? r : 0;
            float l0 = lo[ro * 65 + tx];         // col 2tx-1 (tx=0 -> -inf pad)
            float l1 = le[ro * 64 + tx];         // col 2tx
            float l2 = lo[ro * 65 + tx + 1];     // col 2tx+1
            float s3 = f_ex2(p * l0) + f_ex2(p * l1) + f_ex2(p * l2);
            sum += rv ? s3 : 0.f;
        }

        float mean = fmaf(sum, (1.0f / 9.0f), 1e-12f);
        float res  = f_ex2(f_lg2(mean) * f_rcp(p));

        const size_t o = ((size_t)plane * HO + ho) * WO + tx;
        out_res[o] = res;
        out_p[o]   = p;
    }
}

extern "C" void kernel_launch(void* const* d_in, const int* in_sizes, int n_in,
                              void* d_out, int out_size) {
    const float* bottom = (const float*)d_in[0];
    const float* w1     = (const float*)d_in[1];
    const float* a1     = (const float*)d_in[2];
    const float* w2     = (const float*)d_in[3];
    const float* b2     = (const float*)d_in[4];
    float* out = (float*)d_out;
    const size_t N = (size_t)BATCH * CH * HO * WO;   // elements per output tensor

    cudaFuncSetAttribute(fused_ppool_kernel,
                         cudaFuncAttributeMaxDynamicSharedMemorySize, SMEM_BYTES);

    dim3 blk(64, 16);
    fused_ppool_kernel<<<NPLANES, blk, SMEM_BYTES>>>(bottom, w1, a1, w2, b2,
                                                     out, out + N);

    (void)in_sizes; (void)n_in; (void)out_size;
}

// round 9
// speedup vs baseline: 2.0019x; 1.2140x over previous
#include <cuda_runtime.h>

// Problem shape (fixed by the dataset)
#define BATCH 8
#define CH    256
#define HH    128
#define WW    128
#define HO    64
#define WO    64
#define NPLANES 2048

// Dynamic smem layout (floats). Log tables are row-padded: input row r is
// stored at table row r+1; table row 0 (= input row -1) is -inf so windows
// that stick out the top contribute ex2(-inf) = 0 with no predication.
//   le[129][64] : log2(relu(even cols)), le[r+1][k] = col 2k
//   lo[129][65] : log2(relu(odd cols)),  lo[r+1][j] = col 2j-1 (j=0 = left pad)
//   sc[48]      : [0..31] warp max partials, [32] invm, [33..41] w1 raw
#define LE_OFF 0
#define LO_OFF (129 * 64)
#define SC_OFF (LO_OFF + 129 * 65)
#define SMEM_FLOATS (SC_OFF + 48)
#define SMEM_BYTES  (SMEM_FLOATS * 4)

#define NINF __int_as_float(0xff800000)

__device__ __forceinline__ float f_lg2(float x) {
    float y; asm("lg2.approx.f32 %0, %1;" : "=f"(y) : "f"(x)); return y;
}
__device__ __forceinline__ float f_ex2(float x) {
    float y; asm("ex2.approx.f32 %0, %1;" : "=f"(y) : "f"(x)); return y;
}
__device__ __forceinline__ float f_rcp(float x) {
    float y; asm("rcp.approx.f32 %0, %1;" : "=f"(y) : "f"(x)); return y;
}

// One block = one (b,c) plane. 1024 threads = (64, 16).
// Phase 1: stream plane once, build padded log table in smem + plane max.
// Phase 2: 4 outputs/thread; conv from L2-resident gmem, pooling from smem.
__global__ __launch_bounds__(1024, 2) void fused_ppool_kernel(
    const float* __restrict__ bottom,
    const float* __restrict__ w1,
    const float* __restrict__ a1,
    const float* __restrict__ w2,
    const float* __restrict__ b2,
    float* __restrict__ out_res,
    float* __restrict__ out_p)
{
    extern __shared__ float smem[];
    float* le = smem + LE_OFF;
    float* lo = smem + LO_OFF;
    float* sc = smem + SC_OFF;

    const int plane = blockIdx.x;
    const int c = plane & (CH - 1);
    const float* __restrict__ src = bottom + (size_t)plane * (HH * WW);

    const int tx = threadIdx.x;          // 0..63 -> wo
    const int ty = threadIdx.y;          // 0..15
    const int t  = ty * 64 + tx;         // 0..1023
    const int wid = t >> 5, lid = t & 31;

    if (t < 9)   sc[33 + t] = __ldg(&w1[c * 9 + t]);
    // Pads: table row 0 (input row -1) + odd col -1 for all rows -> -inf
    if (t < 64)               le[t]            = NINF;   // pad row, even cols
    if (t < 129)              lo[t * 65]       = NINF;   // col -1, all rows
    if (t >= 129 && t < 193)  lo[t - 128]      = NINF;   // pad row, odd cols 1..64

    // ---- Phase 1: plane streaming (8192 float2), log table + |x| max ----
    const float2* s2 = (const float2*)src;
    float mx = 0.f;
    #pragma unroll
    for (int i = 0; i < 8; i++) {
        int idx = t + i * 1024;          // float2 index: row = idx>>6, k = idx&63
        int r = idx >> 6, k = idx & 63;
        float2 v = __ldg(s2 + idx);
        le[(r + 1) * 64 + k]     = f_lg2(fmaxf(v.x, 0.f));   // lg2(0) = -inf
        lo[(r + 1) * 65 + k + 1] = f_lg2(fmaxf(v.y, 0.f));
        mx = fmaxf(mx, fmaxf(fabsf(v.x), fabsf(v.y)));
    }
    #pragma unroll
    for (int o = 16; o; o >>= 1) mx = fmaxf(mx, __shfl_xor_sync(0xffffffffu, mx, o));
    if (lid == 0) sc[wid] = mx;
    __syncthreads();
    if (t < 32) {
        float m = sc[t];
        #pragma unroll
        for (int o = 16; o; o >>= 1) m = fmaxf(m, __shfl_xor_sync(0xffffffffu, m, o));
        if (t == 0) sc[32] = 1.0f / (m + 1.0f);
    }
    __syncthreads();

    const float invm = sc[32];
    float w[9];
    #pragma unroll
    for (int i = 0; i < 9; i++) w[i] = sc[33 + i];
    const float av = __ldg(&a1[c]);
    const float wv = __ldg(&w2[c]);
    const float bv = __ldg(&b2[c]);

    // ---- Phase 2: 4 vertically-adjacent outputs per thread ----
    #pragma unroll
    for (int g = 0; g < 4; g++) {
        const int ho = (ty << 2) + g;
        const int rbase = 2 * ho - 1;        // top tap input row (can be -1)

        // conv taps from gmem (L2-hot): per row one LDG.64 (cols 2tx,2tx+1)
        // and one LDG.32 (col 2tx-1). Only ho=0's first row is out of range.
        const float* srow = src + rbase * WW + 2 * tx;
        float conv = 0.f;
        #pragma unroll
        for (int ki = 0; ki < 3; ki++) {
            bool rv = (rbase + ki) >= 0;
            float  v0  = (rv && tx > 0) ? __ldg(srow - 1) : 0.f;
            float2 v12 = rv ? __ldg((const float2*)srow) : make_float2(0.f, 0.f);
            conv = fmaf(w[ki * 3 + 0], v0,    conv);
            conv = fmaf(w[ki * 3 + 1], v12.x, conv);
            conv = fmaf(w[ki * 3 + 2], v12.y, conv);
            srow += WW;
        }
        conv *= invm;                        // conv(x/m) = invm * conv_raw(x)

        // PReLU + per-channel affine + clamp -> exponent p
        float x = conv > 0.f ? conv : av * conv;
        float p = fmaf(x, wv, bv);
        p = fminf(fmaxf(p, 1.0f), 110.0f);

        // Power-mean over the 3x3 window (padded tables: no predication).
        // Table rows for this window: 2ho, 2ho+1, 2ho+2.
        const float* lr = le + (2 * ho) * 64 + tx;
        const float* orow = lo + (2 * ho) * 65 + tx;
        float sum = 0.f;
        #pragma unroll
        for (int ki = 0; ki < 3; ki++) {
            sum += f_ex2(p * orow[0]);       // col 2tx-1
            sum += f_ex2(p * lr[0]);         // col 2tx
            sum += f_ex2(p * orow[1]);       // col 2tx+1
            lr += 64; orow += 65;
        }

        float mean = fmaf(sum, (1.0f / 9.0f), 1e-12f);
        float res  = f_ex2(f_lg2(mean) * f_rcp(p));

        const size_t o = ((size_t)plane * HO + ho) * WO + tx;
        out_res[o] = res;
        out_p[o]   = p;
    }
}

extern "C" void kernel_launch(void* const* d_in, const int* in_sizes, int n_in,
                              void* d_out, int out_size) {
    const float* bottom = (const float*)d_in[0];
    const float* w1     = (const float*)d_in[1];
    const float* a1     = (const float*)d_in[2];
    const float* w2     = (const float*)d_in[3];
    const float* b2     = (const float*)d_in[4];
    float* out = (float*)d_out;
    const size_t N = (size_t)BATCH * CH * HO * WO;   // elements per output tensor

    cudaFuncSetAttribute(fused_ppool_kernel,
                         cudaFuncAttributeMaxDynamicSharedMemorySize, SMEM_BYTES);

    dim3 blk(64, 16);
    fused_ppool_kernel<<<NPLANES, blk, SMEM_BYTES>>>(bottom, w1, a1, w2, b2,
                                                     out, out + N);

    (void)in_sizes; (void)n_in; (void)out_size;
}